// round 4
// baseline (speedup 1.0000x reference)
#include <cuda_runtime.h>
#include <cstdint>
#include <cstddef>

#define NB 64
#define NT 512
#define NH 1024
#define GRID2 128

#define GATE_STRIDE 33554432u  // 512*64*1024

__device__ float    g_gates[4u * GATE_STRIDE];  // [gate][t][b][h]
__device__ unsigned g_hA[2][NB * NH];           // h in tf32, MMA-fragment order, double-buffered
__device__ unsigned g_flags[GRID2 * 8];         // per-CTA barrier flags (32B apart)

__device__ __forceinline__ unsigned f2tf(float f) {
    unsigned r;
    asm("cvt.rna.tf32.f32 %0, %1;" : "=r"(r) : "f"(f));
    return r;
}

__device__ __forceinline__ void mma8(float c[4], const unsigned a[4], const unsigned b[2]) {
    asm volatile(
        "mma.sync.aligned.m16n8k8.row.col.f32.tf32.tf32.f32 "
        "{%0,%1,%2,%3},{%4,%5,%6,%7},{%8,%9},{%0,%1,%2,%3};\n"
        : "+f"(c[0]), "+f"(c[1]), "+f"(c[2]), "+f"(c[3])
        : "r"(a[0]), "r"(a[1]), "r"(a[2]), "r"(a[3]), "r"(b[0]), "r"(b[1]));
}

__device__ __forceinline__ void cp16(unsigned dst, const float* src) {
    asm volatile("cp.async.ca.shared.global [%0], [%1], 16;\n" :: "r"(dst), "l"(src));
}

__device__ __forceinline__ float sig_f(float z) {
    return __fdividef(1.0f, 1.0f + __expf(-z));
}
__device__ __forceinline__ float tanh_f(float z) {
    return __fdividef(2.0f, 1.0f + __expf(-2.0f * z)) - 1.0f;
}

// ---------------------------------------------------------------------------
// Phase 1: gate preactivations  g_gates[g][t][b][h] = x @ W_xg + b_g
// (unchanged from round 3 — works, ~1ms)
// ---------------------------------------------------------------------------
#define P1_SA 36
#define P1_SB 136
#define P1_SMEM ((2 * 128 * P1_SA + 2 * 32 * P1_SB) * 4)

__global__ void __launch_bounds__(256, 2) lstm_xproj(
    const float* __restrict__ x,
    const float* __restrict__ Wxi, const float* __restrict__ Wxf,
    const float* __restrict__ Wxc, const float* __restrict__ Wxo,
    const float* __restrict__ bi,  const float* __restrict__ bf,
    const float* __restrict__ bc,  const float* __restrict__ bo)
{
    extern __shared__ float p1s[];
    float* As = p1s;
    float* Bs = p1s + 2 * 128 * P1_SA;

    const int tid = threadIdx.x;

    if (blockIdx.x == 0 && blockIdx.y == 0) {
        uint4 z4 = make_uint4(0u, 0u, 0u, 0u);
        uint4* hb4 = (uint4*)g_hA[0];
#pragma unroll 4
        for (int i = tid; i < (NB * NH) / 4; i += 256) hb4[i] = z4;
        for (int i = tid; i < GRID2 * 8; i += 256) g_flags[i] = 0u;
    }

    const int lane = tid & 31;
    const int w    = tid >> 5;
    const int mi   = w & 1;
    const int nj   = w >> 1;

    const int mblk  = blockIdx.y;
    const int nglob = blockIdx.x * 128;
    const int gate  = nglob >> 10;
    const int hbase = nglob & 1023;

    const float* W    = (gate == 0) ? Wxi : (gate == 1) ? Wxf : (gate == 2) ? Wxc : Wxo;
    const float* bias = (gate == 0) ? bi  : (gate == 1) ? bf  : (gate == 2) ? bc  : bo;

    const int a_row = tid >> 3, a_c4 = tid & 7;
    const int b_k   = tid >> 5, b_c4 = tid & 31;
    const unsigned As_u = (unsigned)__cvta_generic_to_shared(As);
    const unsigned Bs_u = (unsigned)__cvta_generic_to_shared(Bs);

    float acc[4][4][4];
#pragma unroll
    for (int a = 0; a < 4; a++)
#pragma unroll
        for (int b = 0; b < 4; b++)
#pragma unroll
            for (int c = 0; c < 4; c++) acc[a][b][c] = 0.0f;

    {
#pragma unroll
        for (int i = 0; i < 4; i++) {
            int row = a_row + 32 * i;
            cp16(As_u + (row * P1_SA + a_c4 * 4) * 4,
                 x + (size_t)(mblk * 128 + row) * 1024 + a_c4 * 4);
            int k = b_k + 8 * i;
            cp16(Bs_u + (k * P1_SB + b_c4 * 4) * 4,
                 W + (size_t)k * 1024 + hbase + b_c4 * 4);
        }
        asm volatile("cp.async.commit_group;\n");
    }

#pragma unroll 1
    for (int kt = 0; kt < 32; ++kt) {
        asm volatile("cp.async.wait_group 0;\n");
        __syncthreads();

        if (kt + 1 < 32) {
            int s = (kt + 1) & 1;
#pragma unroll
            for (int i = 0; i < 4; i++) {
                int row = a_row + 32 * i;
                cp16(As_u + (s * 128 * P1_SA + row * P1_SA + a_c4 * 4) * 4,
                     x + (size_t)(mblk * 128 + row) * 1024 + (kt + 1) * 32 + a_c4 * 4);
                int k = b_k + 8 * i;
                cp16(Bs_u + (s * 32 * P1_SB + k * P1_SB + b_c4 * 4) * 4,
                     W + (size_t)((kt + 1) * 32 + k) * 1024 + hbase + b_c4 * 4);
            }
            asm volatile("cp.async.commit_group;\n");
        }

        const float* Ab = As + (kt & 1) * 128 * P1_SA;
        const float* Bb = Bs + (kt & 1) * 32 * P1_SB;

#pragma unroll
        for (int q = 0; q < 4; q++) {
            const int kk = q * 8;
            unsigned afr[4][4], bfr[4][2];
#pragma unroll
            for (int mt = 0; mt < 4; mt++) {
                int r = mi * 64 + mt * 16 + (lane >> 2);
                int c = kk + (lane & 3);
                afr[mt][0] = f2tf(Ab[r * P1_SA + c]);
                afr[mt][1] = f2tf(Ab[(r + 8) * P1_SA + c]);
                afr[mt][2] = f2tf(Ab[r * P1_SA + c + 4]);
                afr[mt][3] = f2tf(Ab[(r + 8) * P1_SA + c + 4]);
            }
#pragma unroll
            for (int nt = 0; nt < 4; nt++) {
                int nb = nj * 32 + nt * 8 + (lane >> 2);
                int kr = kk + (lane & 3);
                bfr[nt][0] = f2tf(Bb[kr * P1_SB + nb]);
                bfr[nt][1] = f2tf(Bb[(kr + 4) * P1_SB + nb]);
            }
#pragma unroll
            for (int mt = 0; mt < 4; mt++)
#pragma unroll
                for (int nt = 0; nt < 4; nt++)
                    mma8(acc[mt][nt], afr[mt], bfr[nt]);
        }
    }

    float* gbuf = g_gates + (size_t)gate * GATE_STRIDE;
#pragma unroll
    for (int mt = 0; mt < 4; mt++) {
#pragma unroll
        for (int nt = 0; nt < 4; nt++) {
#pragma unroll
            for (int rr = 0; rr < 2; rr++) {
                int m   = mblk * 128 + mi * 64 + mt * 16 + (lane >> 2) + rr * 8;
                int col = nj * 32 + nt * 8 + (lane & 3) * 2;
                int h   = hbase + col;
                int b   = m >> 9;
                int t   = m & 511;
                float2 o;
                o.x = acc[mt][nt][rr * 2 + 0] + __ldg(bias + h);
                o.y = acc[mt][nt][rr * 2 + 1] + __ldg(bias + h + 1);
                *(float2*)(gbuf + (size_t)t * 65536 + (size_t)b * 1024 + h) = o;
            }
        }
    }
}

// ---------------------------------------------------------------------------
// Phase 2: persistent recurrence. 128 CTAs x 512 threads. CTA owns h-cols
// [blk*8, blk*8+8) across 4 gates (N=32). W_h in SMEM (tf32, stride 40).
// 16 warps = 16 K-groups, warp tile m64 n32 k64: b-fragments loaded ONCE
// and reused across 4 m-tiles (4x LDS cut vs round 3). a-fragments LDG.128
// from L2 in fragment order (disjoint per warp). 16 partial z reduced in
// 4 SMEM buffers over 4 phases.
// ---------------------------------------------------------------------------
#define P2_SW 40
#define P2_SZ 40
#define SMEM2_BYTES ((1024 * P2_SW + 4 * 64 * P2_SZ + 512) * 4)

__global__ void __launch_bounds__(512, 1) lstm_rec(
    const float* __restrict__ Whi, const float* __restrict__ Whf,
    const float* __restrict__ Whc, const float* __restrict__ Who,
    float* __restrict__ out)
{
    extern __shared__ unsigned char smem_raw[];
    unsigned* Wsm  = (unsigned*)smem_raw;            // [1024][40]
    float*    zred = (float*)(Wsm + 1024 * P2_SW);   // [4][64][40]
    float*    csm  = zred + 4 * 64 * P2_SZ;          // [512]

    const int tid  = threadIdx.x;
    const int lane = tid & 31;
    const int ks   = tid >> 5;   // warp = K group, k in [ks*64, ks*64+64)
    const int blk  = blockIdx.x;
    const int hb   = blk * 8;

    // weight slice -> SMEM (tf32), once
    {
        const float* Wg[4] = {Whi, Whf, Whc, Who};
        for (int idx = tid; idx < 4096; idx += 512) {
            int g = idx >> 10, k = idx & 1023;
            const float* src = Wg[g] + (size_t)k * 1024 + hb;
            float4 v0 = *(const float4*)(src);
            float4 v1 = *(const float4*)(src + 4);
            unsigned* d = &Wsm[k * P2_SW + g * 8];
            d[0] = f2tf(v0.x); d[1] = f2tf(v0.y); d[2] = f2tf(v0.z); d[3] = f2tf(v0.w);
            d[4] = f2tf(v1.x); d[5] = f2tf(v1.y); d[6] = f2tf(v1.z); d[7] = f2tf(v1.w);
        }
        csm[tid] = 0.0f;
    }

    // consumer a-fragment base: slot S = (ks*8 + q)*4 + mi, word = S*128 + lane*4
    const int cbase = ks * 4096 + lane * 4;     // + q*512 + mi*128

    // elementwise coords + producer scatter index
    const int em = tid >> 3, ej = tid & 7;
    const int hcol = hb + ej;
    int p_widx;
    {
        int row = em, col = hcol;
        int pmi = row >> 4, rb = row & 15, hi_r = rb >> 3, lr = rb & 7;
        int pks = col >> 6, c6 = col & 63;
        int pq  = c6 >> 3,  hi_c = (c6 >> 2) & 1, l2 = c6 & 3;
        int plane = lr * 4 + l2;
        int j = hi_r + 2 * hi_c;
        int S = (pks * 8 + pq) * 4 + pmi;
        p_widx = S * 128 + plane * 4 + j;
    }

    const int l3   = lane & 3;
    const int nbb  = lane >> 2;

    __syncthreads();

#pragma unroll 1
    for (int t = 0; t < NT; ++t) {
        const unsigned* hA = g_hA[t & 1];
        unsigned*       hN = g_hA[(t + 1) & 1];

        // prefetch this step's gate preactivations
        const size_t gidx = (size_t)t * 65536 + (size_t)em * 1024 + hcol;
        const float gi = __ldg(g_gates + gidx);
        const float gf = __ldg(g_gates + GATE_STRIDE + gidx);
        const float gc = __ldg(g_gates + 2u * GATE_STRIDE + gidx);
        const float go = __ldg(g_gates + 3u * GATE_STRIDE + gidx);

        float acc[4][4][4];
#pragma unroll
        for (int a = 0; a < 4; a++)
#pragma unroll
            for (int b = 0; b < 4; b++)
#pragma unroll
                for (int c = 0; c < 4; c++) acc[a][b][c] = 0.0f;

        // a-fragment prefetch: q0 -> abuf[0]
        uint4 abuf[2][4];
#pragma unroll
        for (int mi = 0; mi < 4; mi++)
            abuf[0][mi] = __ldcg((const uint4*)(hA + cbase + mi * 128));

#pragma unroll
        for (int q = 0; q < 8; ++q) {
            if (q + 1 < 8) {
#pragma unroll
                for (int mi = 0; mi < 4; mi++)
                    abuf[(q + 1) & 1][mi] =
                        __ldcg((const uint4*)(hA + cbase + (q + 1) * 512 + mi * 128));
            }

            // b-fragments: loaded once, reused across 4 m-tiles
            const int kgb = ks * 64 + q * 8 + l3;
            const unsigned* wrow = Wsm + kgb * P2_SW;
            unsigned bfr[4][2];
#pragma unroll
            for (int nt = 0; nt < 4; nt++) {
                bfr[nt][0] = wrow[nt * 8 + nbb];
                bfr[nt][1] = wrow[4 * P2_SW + nt * 8 + nbb];
            }

#pragma unroll
            for (int mi = 0; mi < 4; mi++) {
                const uint4 av = abuf[q & 1][mi];
                unsigned afr[4] = {av.x, av.y, av.z, av.w};
#pragma unroll
                for (int nt = 0; nt < 4; nt++)
                    mma8(acc[mi][nt], afr, bfr[nt]);
            }
        }

        // ---- 16-way reduction in 4 buffers / 4 phases ----
        const int ph = ks >> 2, zb = ks & 3;
        float* z = zred + zb * 64 * P2_SZ;

        if (ph == 0) {
#pragma unroll
            for (int mi = 0; mi < 4; mi++)
#pragma unroll
                for (int nt = 0; nt < 4; nt++)
#pragma unroll
                    for (int rr = 0; rr < 2; rr++) {
                        int r = mi * 16 + (lane >> 2) + rr * 8;
                        int c = nt * 8 + (lane & 3) * 2;
                        *(float2*)&z[r * P2_SZ + c] =
                            make_float2(acc[mi][nt][rr * 2], acc[mi][nt][rr * 2 + 1]);
                    }
        }
        __syncthreads();
#pragma unroll 1
        for (int p = 1; p < 4; ++p) {
            if (ph == p) {
#pragma unroll
                for (int mi = 0; mi < 4; mi++)
#pragma unroll
                    for (int nt = 0; nt < 4; nt++)
#pragma unroll
                        for (int rr = 0; rr < 2; rr++) {
                            int r = mi * 16 + (lane >> 2) + rr * 8;
                            int c = nt * 8 + (lane & 3) * 2;
                            float2 old = *(float2*)&z[r * P2_SZ + c];
                            old.x += acc[mi][nt][rr * 2];
                            old.y += acc[mi][nt][rr * 2 + 1];
                            *(float2*)&z[r * P2_SZ + c] = old;
                        }
            }
            __syncthreads();
        }

        // ---- elementwise LSTM cell update: one element per thread ----
        {
            const int zo_idx = em * P2_SZ + ej;
            const int ZB = 64 * P2_SZ;
            float zi = zred[zo_idx]           + zred[ZB + zo_idx]
                     + zred[2 * ZB + zo_idx]  + zred[3 * ZB + zo_idx] + gi;
            float zf = zred[zo_idx + 8]           + zred[ZB + zo_idx + 8]
                     + zred[2 * ZB + zo_idx + 8]  + zred[3 * ZB + zo_idx + 8] + gf;
            float zc = zred[zo_idx + 16]          + zred[ZB + zo_idx + 16]
                     + zred[2 * ZB + zo_idx + 16] + zred[3 * ZB + zo_idx + 16] + gc;
            float zo = zred[zo_idx + 24]          + zred[ZB + zo_idx + 24]
                     + zred[2 * ZB + zo_idx + 24] + zred[3 * ZB + zo_idx + 24] + go;
            float iv = sig_f(zi);
            float fv = sig_f(zf);
            float cv = tanh_f(zc);
            float ov = sig_f(zo);
            float cnew = fv * csm[tid] + iv * cv;
            csm[tid] = cnew;
            float hv = ov * tanh_f(cnew);
            hN[p_widx] = f2tf(hv);
            out[(size_t)em * 524288 + (size_t)t * 1024 + hcol] = hv;
            if (t == NT - 1) {
                out[33554432u + (size_t)em * 1024 + hcol] = hv;
                out[33554432u + 65536u + (size_t)em * 1024 + hcol] = cnew;
            }
        }

        // ---- distributed grid barrier ----
        __syncthreads();
        if (tid == 0) {
            __threadfence();
            *(volatile unsigned*)&g_flags[blk * 8] = (unsigned)(t + 1);
        }
        if (tid < GRID2) {
            while (*(volatile unsigned*)&g_flags[tid * 8] < (unsigned)(t + 1)) { }
            __threadfence();
        }
        __syncthreads();
    }
}

// ---------------------------------------------------------------------------
extern "C" void kernel_launch(void* const* d_in, const int* in_sizes, int n_in,
                              void* d_out, int out_size)
{
    const float* x   = (const float*)d_in[0];
    const float* Wxi = (const float*)d_in[1];
    const float* Whi = (const float*)d_in[2];
    const float* bi  = (const float*)d_in[3];
    const float* Wxf = (const float*)d_in[4];
    const float* Whf = (const float*)d_in[5];
    const float* bf  = (const float*)d_in[6];
    const float* Wxc = (const float*)d_in[7];
    const float* Whc = (const float*)d_in[8];
    const float* bc  = (const float*)d_in[9];
    const float* Wxo = (const float*)d_in[10];
    const float* Who = (const float*)d_in[11];
    const float* bo  = (const float*)d_in[12];
    float* out = (float*)d_out;

    cudaFuncSetAttribute(lstm_xproj, cudaFuncAttributeMaxDynamicSharedMemorySize, P1_SMEM);
    cudaFuncSetAttribute(lstm_rec,   cudaFuncAttributeMaxDynamicSharedMemorySize, SMEM2_BYTES);

    dim3 g1(32, 256);
    lstm_xproj<<<g1, 256, P1_SMEM>>>(x, Wxi, Wxf, Wxc, Wxo, bi, bf, bc, bo);

    lstm_rec<<<GRID2, 512, SMEM2_BYTES>>>(Whi, Whf, Whc, Who, out);
}

// round 5
// speedup vs baseline: 1.0429x; 1.0429x over previous
#include <cuda_runtime.h>
#include <cstdint>
#include <cstddef>

#define NB 64
#define NT 512
#define NH 1024
#define GRID2 128

#define GATE_STRIDE 33554432u  // 512*64*1024

__device__ float    g_gates[4u * GATE_STRIDE];  // [gate][t][b][h]
__device__ unsigned g_hA[2][NB * NH];           // h in tf32, MMA-fragment order, double-buffered
__device__ unsigned g_flags[GRID2 * 8];         // per-CTA "h(v) written" flags (32B apart)
__device__ unsigned g_rd[GRID2 * 8];            // per-CTA "read steps < v done" flags

__device__ __forceinline__ unsigned f2tf(float f) {
    unsigned r;
    asm("cvt.rna.tf32.f32 %0, %1;" : "=r"(r) : "f"(f));
    return r;
}

__device__ __forceinline__ void mma8(float c[4], const unsigned a[4], const unsigned b[2]) {
    asm volatile(
        "mma.sync.aligned.m16n8k8.row.col.f32.tf32.tf32.f32 "
        "{%0,%1,%2,%3},{%4,%5,%6,%7},{%8,%9},{%0,%1,%2,%3};\n"
        : "+f"(c[0]), "+f"(c[1]), "+f"(c[2]), "+f"(c[3])
        : "r"(a[0]), "r"(a[1]), "r"(a[2]), "r"(a[3]), "r"(b[0]), "r"(b[1]));
}

__device__ __forceinline__ void cp16(unsigned dst, const float* src) {
    asm volatile("cp.async.ca.shared.global [%0], [%1], 16;\n" :: "r"(dst), "l"(src));
}

__device__ __forceinline__ float sig_f(float z) {
    return __fdividef(1.0f, 1.0f + __expf(-z));
}
__device__ __forceinline__ float tanh_f(float z) {
    return __fdividef(2.0f, 1.0f + __expf(-2.0f * z)) - 1.0f;
}

// ---------------------------------------------------------------------------
// Phase 1: gate preactivations. A-side fed as raw fp32 (HW tf32 truncation),
// B-side RNA-converted. cp.async double-buffered, 128x128x32 tiles.
// ---------------------------------------------------------------------------
#define P1_SA 36
#define P1_SB 136
#define P1_SMEM ((2 * 128 * P1_SA + 2 * 32 * P1_SB) * 4)

__global__ void __launch_bounds__(256, 2) lstm_xproj(
    const float* __restrict__ x,
    const float* __restrict__ Wxi, const float* __restrict__ Wxf,
    const float* __restrict__ Wxc, const float* __restrict__ Wxo,
    const float* __restrict__ bi,  const float* __restrict__ bf,
    const float* __restrict__ bc,  const float* __restrict__ bo)
{
    extern __shared__ float p1s[];
    float* As = p1s;
    float* Bs = p1s + 2 * 128 * P1_SA;

    const int tid = threadIdx.x;

    // per-replay init: h0 fragments = 0, all flags = 0
    if (blockIdx.x == 0 && blockIdx.y == 0) {
        uint4 z4 = make_uint4(0u, 0u, 0u, 0u);
        uint4* hb4 = (uint4*)g_hA[0];
#pragma unroll 4
        for (int i = tid; i < (NB * NH) / 4; i += 256) hb4[i] = z4;
        for (int i = tid; i < GRID2 * 8; i += 256) { g_flags[i] = 0u; g_rd[i] = 0u; }
    }

    const int lane = tid & 31;
    const int w    = tid >> 5;
    const int mi   = w & 1;
    const int nj   = w >> 1;

    const int mblk  = blockIdx.y;
    const int nglob = blockIdx.x * 128;
    const int gate  = nglob >> 10;
    const int hbase = nglob & 1023;

    const float* W    = (gate == 0) ? Wxi : (gate == 1) ? Wxf : (gate == 2) ? Wxc : Wxo;
    const float* bias = (gate == 0) ? bi  : (gate == 1) ? bf  : (gate == 2) ? bc  : bo;

    const int a_row = tid >> 3, a_c4 = tid & 7;
    const int b_k   = tid >> 5, b_c4 = tid & 31;
    const unsigned As_u = (unsigned)__cvta_generic_to_shared(As);
    const unsigned Bs_u = (unsigned)__cvta_generic_to_shared(Bs);

    float acc[4][4][4];
#pragma unroll
    for (int a = 0; a < 4; a++)
#pragma unroll
        for (int b = 0; b < 4; b++)
#pragma unroll
            for (int c = 0; c < 4; c++) acc[a][b][c] = 0.0f;

    {
#pragma unroll
        for (int i = 0; i < 4; i++) {
            int row = a_row + 32 * i;
            cp16(As_u + (row * P1_SA + a_c4 * 4) * 4,
                 x + (size_t)(mblk * 128 + row) * 1024 + a_c4 * 4);
            int k = b_k + 8 * i;
            cp16(Bs_u + (k * P1_SB + b_c4 * 4) * 4,
                 W + (size_t)k * 1024 + hbase + b_c4 * 4);
        }
        asm volatile("cp.async.commit_group;\n");
    }

#pragma unroll 1
    for (int kt = 0; kt < 32; ++kt) {
        asm volatile("cp.async.wait_group 0;\n");
        __syncthreads();

        if (kt + 1 < 32) {
            int s = (kt + 1) & 1;
#pragma unroll
            for (int i = 0; i < 4; i++) {
                int row = a_row + 32 * i;
                cp16(As_u + (s * 128 * P1_SA + row * P1_SA + a_c4 * 4) * 4,
                     x + (size_t)(mblk * 128 + row) * 1024 + (kt + 1) * 32 + a_c4 * 4);
                int k = b_k + 8 * i;
                cp16(Bs_u + (s * 32 * P1_SB + k * P1_SB + b_c4 * 4) * 4,
                     W + (size_t)((kt + 1) * 32 + k) * 1024 + hbase + b_c4 * 4);
            }
            asm volatile("cp.async.commit_group;\n");
        }

        const float* Ab = As + (kt & 1) * 128 * P1_SA;
        const float* Bb = Bs + (kt & 1) * 32 * P1_SB;

#pragma unroll
        for (int q = 0; q < 4; q++) {
            const int kk = q * 8;
            unsigned afr[4][4], bfr[4][2];
#pragma unroll
            for (int mt = 0; mt < 4; mt++) {
                int r = mi * 64 + mt * 16 + (lane >> 2);
                int c = kk + (lane & 3);
                // raw fp32 bits: HW truncates to tf32 (CUTLASS fast path)
                afr[mt][0] = __float_as_uint(Ab[r * P1_SA + c]);
                afr[mt][1] = __float_as_uint(Ab[(r + 8) * P1_SA + c]);
                afr[mt][2] = __float_as_uint(Ab[r * P1_SA + c + 4]);
                afr[mt][3] = __float_as_uint(Ab[(r + 8) * P1_SA + c + 4]);
            }
#pragma unroll
            for (int nt = 0; nt < 4; nt++) {
                int nb = nj * 32 + nt * 8 + (lane >> 2);
                int kr = kk + (lane & 3);
                bfr[nt][0] = f2tf(Bb[kr * P1_SB + nb]);
                bfr[nt][1] = f2tf(Bb[(kr + 4) * P1_SB + nb]);
            }
#pragma unroll
            for (int mt = 0; mt < 4; mt++)
#pragma unroll
                for (int nt = 0; nt < 4; nt++)
                    mma8(acc[mt][nt], afr[mt], bfr[nt]);
        }
    }

    float* gbuf = g_gates + (size_t)gate * GATE_STRIDE;
#pragma unroll
    for (int mt = 0; mt < 4; mt++) {
#pragma unroll
        for (int nt = 0; nt < 4; nt++) {
#pragma unroll
            for (int rr = 0; rr < 2; rr++) {
                int m   = mblk * 128 + mi * 64 + mt * 16 + (lane >> 2) + rr * 8;
                int col = nj * 32 + nt * 8 + (lane & 3) * 2;
                int h   = hbase + col;
                int b   = m >> 9;
                int t   = m & 511;
                float2 o;
                o.x = acc[mt][nt][rr * 2 + 0] + __ldg(bias + h);
                o.y = acc[mt][nt][rr * 2 + 1] + __ldg(bias + h + 1);
                *(float2*)(gbuf + (size_t)t * 65536 + (size_t)b * 1024 + h) = o;
            }
        }
    }
}

// ---------------------------------------------------------------------------
// Phase 2: persistent recurrence, DATAFLOW-SYNCED (no global barrier).
// 128 CTAs x 512 threads, CTA owns h-cols [blk*8,+8) across 4 gates (N=32).
// 16 warps = 16 K-groups, warp tile m64n32k64 (b-frags loaded once/warp).
// Warp ks waits only on its 8 producer CTAs' flags; WAR protected by
// read-done flags polled overlapping the reduction phases.
// ---------------------------------------------------------------------------
#define P2_SW 40
#define P2_SZ 40
#define SMEM2_BYTES ((1024 * P2_SW + 4 * 64 * P2_SZ + 512) * 4)

__global__ void __launch_bounds__(512, 1) lstm_rec(
    const float* __restrict__ Whi, const float* __restrict__ Whf,
    const float* __restrict__ Whc, const float* __restrict__ Who,
    float* __restrict__ out)
{
    extern __shared__ unsigned char smem_raw[];
    unsigned* Wsm  = (unsigned*)smem_raw;            // [1024][40]
    float*    zred = (float*)(Wsm + 1024 * P2_SW);   // [4][64][40]
    float*    csm  = zred + 4 * 64 * P2_SZ;          // [512]

    const int tid  = threadIdx.x;
    const int lane = tid & 31;
    const int ks   = tid >> 5;   // warp = K group, k in [ks*64, ks*64+64)
    const int blk  = blockIdx.x;
    const int hb   = blk * 8;

    // weight slice -> SMEM (tf32), once
    {
        const float* Wg[4] = {Whi, Whf, Whc, Who};
        for (int idx = tid; idx < 4096; idx += 512) {
            int g = idx >> 10, k = idx & 1023;
            const float* src = Wg[g] + (size_t)k * 1024 + hb;
            float4 v0 = *(const float4*)(src);
            float4 v1 = *(const float4*)(src + 4);
            unsigned* d = &Wsm[k * P2_SW + g * 8];
            d[0] = f2tf(v0.x); d[1] = f2tf(v0.y); d[2] = f2tf(v0.z); d[3] = f2tf(v0.w);
            d[4] = f2tf(v1.x); d[5] = f2tf(v1.y); d[6] = f2tf(v1.z); d[7] = f2tf(v1.w);
        }
        csm[tid] = 0.0f;
    }

    // consumer a-fragment base: slot S = (ks*8 + q)*4 + mi, word = S*128 + lane*4
    const int cbase = ks * 4096 + lane * 4;

    // forward-wait flag pointer: producers of warp ks are CTAs [ks*8, ks*8+8)
    const volatile unsigned* fwd_flag = g_flags + (ks * 8 + (lane & 7)) * 8;

    // elementwise coords + producer scatter index
    const int em = tid >> 3, ej = tid & 7;
    const int hcol = hb + ej;
    int p_widx;
    {
        int row = em, col = hcol;
        int pmi = row >> 4, rb = row & 15, hi_r = rb >> 3, lr = rb & 7;
        int pks = col >> 6, c6 = col & 63;
        int pq  = c6 >> 3,  hi_c = (c6 >> 2) & 1, l2 = c6 & 3;
        int plane = lr * 4 + l2;
        int j = hi_r + 2 * hi_c;
        int S = (pks * 8 + pq) * 4 + pmi;
        p_widx = S * 128 + plane * 4 + j;
    }

    const int l3  = lane & 3;
    const int nbb = lane >> 2;

    __syncthreads();

#pragma unroll 1
    for (int t = 0; t < NT; ++t) {
        const unsigned* hA = g_hA[t & 1];
        unsigned*       hN = g_hA[(t + 1) & 1];

        // prefetch this step's gate preactivations
        const size_t gidx = (size_t)t * 65536 + (size_t)em * 1024 + hcol;
        const float gi = __ldg(g_gates + gidx);
        const float gf = __ldg(g_gates + GATE_STRIDE + gidx);
        const float gc = __ldg(g_gates + 2u * GATE_STRIDE + gidx);
        const float go = __ldg(g_gates + 3u * GATE_STRIDE + gidx);

        // ---- forward wait: only this warp's 8 producers ----
        for (;;) {
            unsigned v = *fwd_flag;
            if (__all_sync(0xffffffffu, (int)v >= t)) break;
        }
        __threadfence();

        float acc[4][4][4];
#pragma unroll
        for (int a = 0; a < 4; a++)
#pragma unroll
            for (int b = 0; b < 4; b++)
#pragma unroll
                for (int c = 0; c < 4; c++) acc[a][b][c] = 0.0f;

        uint4 abuf[2][4];
#pragma unroll
        for (int m2 = 0; m2 < 4; m2++)
            abuf[0][m2] = __ldcg((const uint4*)(hA + cbase + m2 * 128));

#pragma unroll
        for (int q = 0; q < 8; ++q) {
            if (q + 1 < 8) {
#pragma unroll
                for (int m2 = 0; m2 < 4; m2++)
                    abuf[(q + 1) & 1][m2] =
                        __ldcg((const uint4*)(hA + cbase + (q + 1) * 512 + m2 * 128));
            }

            const int kgb = ks * 64 + q * 8 + l3;
            const unsigned* wrow = Wsm + kgb * P2_SW;
            unsigned bfr[4][2];
#pragma unroll
            for (int nt = 0; nt < 4; nt++) {
                bfr[nt][0] = wrow[nt * 8 + nbb];
                bfr[nt][1] = wrow[4 * P2_SW + nt * 8 + nbb];
            }

#pragma unroll
            for (int m2 = 0; m2 < 4; m2++) {
                const uint4 av = abuf[q & 1][m2];
                unsigned afr[4] = {av.x, av.y, av.z, av.w};
#pragma unroll
                for (int nt = 0; nt < 4; nt++)
                    mma8(acc[m2][nt], afr, bfr[nt]);
            }
        }

        // ---- reduction phase 0 ----
        const int ph = ks >> 2, zb = ks & 3;
        float* z = zred + zb * 64 * P2_SZ;

        if (ph == 0) {
#pragma unroll
            for (int m2 = 0; m2 < 4; m2++)
#pragma unroll
                for (int nt = 0; nt < 4; nt++)
#pragma unroll
                    for (int rr = 0; rr < 2; rr++) {
                        int r = m2 * 16 + (lane >> 2) + rr * 8;
                        int c = nt * 8 + (lane & 3) * 2;
                        *(float2*)&z[r * P2_SZ + c] =
                            make_float2(acc[m2][nt][rr * 2], acc[m2][nt][rr * 2 + 1]);
                    }
        }
        __syncthreads();   // all warps' a-frag loads consumed by here

        // publish read-done (h(t) consumed), then WAR-gate poll for writing
        // h(t+1) over h(t-1) — overlaps reduction phases 1-3
        if (tid == 0) {
            __threadfence();
            *(volatile unsigned*)&g_rd[blk * 8] = (unsigned)(t + 1);
        }
        if (tid < GRID2) {
            while ((int)(*(volatile unsigned*)&g_rd[tid * 8]) < t) { }
            __threadfence();
        }

#pragma unroll 1
        for (int p = 1; p < 4; ++p) {
            if (ph == p) {
#pragma unroll
                for (int m2 = 0; m2 < 4; m2++)
#pragma unroll
                    for (int nt = 0; nt < 4; nt++)
#pragma unroll
                        for (int rr = 0; rr < 2; rr++) {
                            int r = m2 * 16 + (lane >> 2) + rr * 8;
                            int c = nt * 8 + (lane & 3) * 2;
                            float2 old = *(float2*)&z[r * P2_SZ + c];
                            old.x += acc[m2][nt][rr * 2];
                            old.y += acc[m2][nt][rr * 2 + 1];
                            *(float2*)&z[r * P2_SZ + c] = old;
                        }
            }
            __syncthreads();
        }

        // ---- elementwise LSTM cell update ----
        {
            const int zo_idx = em * P2_SZ + ej;
            const int ZB = 64 * P2_SZ;
            float zi = zred[zo_idx]           + zred[ZB + zo_idx]
                     + zred[2 * ZB + zo_idx]  + zred[3 * ZB + zo_idx] + gi;
            float zf = zred[zo_idx + 8]           + zred[ZB + zo_idx + 8]
                     + zred[2 * ZB + zo_idx + 8]  + zred[3 * ZB + zo_idx + 8] + gf;
            float zc = zred[zo_idx + 16]          + zred[ZB + zo_idx + 16]
                     + zred[2 * ZB + zo_idx + 16] + zred[3 * ZB + zo_idx + 16] + gc;
            float zo = zred[zo_idx + 24]          + zred[ZB + zo_idx + 24]
                     + zred[2 * ZB + zo_idx + 24] + zred[3 * ZB + zo_idx + 24] + go;
            float iv = sig_f(zi);
            float fv = sig_f(zf);
            float cv = tanh_f(zc);
            float ov = sig_f(zo);
            float cnew = fv * csm[tid] + iv * cv;
            csm[tid] = cnew;
            float hv = ov * tanh_f(cnew);
            hN[p_widx] = f2tf(hv);
            out[(size_t)em * 524288 + (size_t)t * 1024 + hcol] = hv;
            if (t == NT - 1) {
                out[33554432u + (size_t)em * 1024 + hcol] = hv;
                out[33554432u + 65536u + (size_t)em * 1024 + hcol] = cnew;
            }
        }

        // ---- release: h(t+1) of this CTA available ----
        __syncthreads();
        if (tid == 0) {
            __threadfence();
            *(volatile unsigned*)&g_flags[blk * 8] = (unsigned)(t + 1);
        }
    }
}

// ---------------------------------------------------------------------------
extern "C" void kernel_launch(void* const* d_in, const int* in_sizes, int n_in,
                              void* d_out, int out_size)
{
    const float* x   = (const float*)d_in[0];
    const float* Wxi = (const float*)d_in[1];
    const float* Whi = (const float*)d_in[2];
    const float* bi  = (const float*)d_in[3];
    const float* Wxf = (const float*)d_in[4];
    const float* Whf = (const float*)d_in[5];
    const float* bf  = (const float*)d_in[6];
    const float* Wxc = (const float*)d_in[7];
    const float* Whc = (const float*)d_in[8];
    const float* bc  = (const float*)d_in[9];
    const float* Wxo = (const float*)d_in[10];
    const float* Who = (const float*)d_in[11];
    const float* bo  = (const float*)d_in[12];
    float* out = (float*)d_out;

    cudaFuncSetAttribute(lstm_xproj, cudaFuncAttributeMaxDynamicSharedMemorySize, P1_SMEM);
    cudaFuncSetAttribute(lstm_rec,   cudaFuncAttributeMaxDynamicSharedMemorySize, SMEM2_BYTES);

    dim3 g1(32, 256);
    lstm_xproj<<<g1, 256, P1_SMEM>>>(x, Wxi, Wxf, Wxc, Wxo, bi, bf, bc, bo);

    lstm_rec<<<GRID2, 512, SMEM2_BYTES>>>(Whi, Whf, Whc, Who, out);
}

// round 8
// speedup vs baseline: 1.1712x; 1.1230x over previous
#include <cuda_runtime.h>
#include <cstdint>
#include <cstddef>

#define NB 64
#define NT 512
#define NH 1024
#define GRID2 128

#define GATE_STRIDE 33554432u  // 512*64*1024

__device__ float    g_gates[4u * GATE_STRIDE];  // [gate][t][b][h]
__device__ unsigned g_hA[2][NB * NH];           // h in tf32, MMA-fragment order, double-buffered
__device__ unsigned g_flags[GRID2 * 8];         // per-CTA "h(v) written" flags (32B apart)
__device__ unsigned g_rd[GRID2 * 8];            // per-CTA "h(v) consumed" flags

__device__ __forceinline__ unsigned f2tf(float f) {
    unsigned r;
    asm("cvt.rna.tf32.f32 %0, %1;" : "=r"(r) : "f"(f));
    return r;
}

__device__ __forceinline__ void mma8(float c[4], const unsigned a[4], const unsigned b[2]) {
    asm volatile(
        "mma.sync.aligned.m16n8k8.row.col.f32.tf32.tf32.f32 "
        "{%0,%1,%2,%3},{%4,%5,%6,%7},{%8,%9},{%0,%1,%2,%3};\n"
        : "+f"(c[0]), "+f"(c[1]), "+f"(c[2]), "+f"(c[3])
        : "r"(a[0]), "r"(a[1]), "r"(a[2]), "r"(a[3]), "r"(b[0]), "r"(b[1]));
}

__device__ __forceinline__ void cp16(unsigned dst, const float* src) {
    asm volatile("cp.async.ca.shared.global [%0], [%1], 16;\n" :: "r"(dst), "l"(src));
}

__device__ __forceinline__ unsigned ld_acq(const unsigned* p) {
    unsigned v;
    asm volatile("ld.acquire.gpu.global.u32 %0, [%1];" : "=r"(v) : "l"(p) : "memory");
    return v;
}

__device__ __forceinline__ float sig_f(float z) {
    return __fdividef(1.0f, 1.0f + __expf(-z));
}
__device__ __forceinline__ float tanh_f(float z) {
    return __fdividef(2.0f, 1.0f + __expf(-2.0f * z)) - 1.0f;
}

// ---------------------------------------------------------------------------
// Phase 1: gate preactivations (unchanged — known good)
// ---------------------------------------------------------------------------
#define P1_SA 36
#define P1_SB 136
#define P1_SMEM ((2 * 128 * P1_SA + 2 * 32 * P1_SB) * 4)

__global__ void __launch_bounds__(256, 2) lstm_xproj(
    const float* __restrict__ x,
    const float* __restrict__ Wxi, const float* __restrict__ Wxf,
    const float* __restrict__ Wxc, const float* __restrict__ Wxo,
    const float* __restrict__ bi,  const float* __restrict__ bf,
    const float* __restrict__ bc,  const float* __restrict__ bo)
{
    extern __shared__ float p1s[];
    float* As = p1s;
    float* Bs = p1s + 2 * 128 * P1_SA;

    const int tid = threadIdx.x;

    if (blockIdx.x == 0 && blockIdx.y == 0) {
        uint4 z4 = make_uint4(0u, 0u, 0u, 0u);
        uint4* hb4 = (uint4*)g_hA[0];
#pragma unroll 4
        for (int i = tid; i < (NB * NH) / 4; i += 256) hb4[i] = z4;
        for (int i = tid; i < GRID2 * 8; i += 256) { g_flags[i] = 0u; g_rd[i] = 0u; }
    }

    const int lane = tid & 31;
    const int w    = tid >> 5;
    const int mi   = w & 1;
    const int nj   = w >> 1;

    const int mblk  = blockIdx.y;
    const int nglob = blockIdx.x * 128;
    const int gate  = nglob >> 10;
    const int hbase = nglob & 1023;

    const float* W    = (gate == 0) ? Wxi : (gate == 1) ? Wxf : (gate == 2) ? Wxc : Wxo;
    const float* bias = (gate == 0) ? bi  : (gate == 1) ? bf  : (gate == 2) ? bc  : bo;

    const int a_row = tid >> 3, a_c4 = tid & 7;
    const int b_k   = tid >> 5, b_c4 = tid & 31;
    const unsigned As_u = (unsigned)__cvta_generic_to_shared(As);
    const unsigned Bs_u = (unsigned)__cvta_generic_to_shared(Bs);

    float acc[4][4][4];
#pragma unroll
    for (int a = 0; a < 4; a++)
#pragma unroll
        for (int b = 0; b < 4; b++)
#pragma unroll
            for (int c = 0; c < 4; c++) acc[a][b][c] = 0.0f;

    {
#pragma unroll
        for (int i = 0; i < 4; i++) {
            int row = a_row + 32 * i;
            cp16(As_u + (row * P1_SA + a_c4 * 4) * 4,
                 x + (size_t)(mblk * 128 + row) * 1024 + a_c4 * 4);
            int k = b_k + 8 * i;
            cp16(Bs_u + (k * P1_SB + b_c4 * 4) * 4,
                 W + (size_t)k * 1024 + hbase + b_c4 * 4);
        }
        asm volatile("cp.async.commit_group;\n");
    }

#pragma unroll 1
    for (int kt = 0; kt < 32; ++kt) {
        asm volatile("cp.async.wait_group 0;\n");
        __syncthreads();

        if (kt + 1 < 32) {
            int s = (kt + 1) & 1;
#pragma unroll
            for (int i = 0; i < 4; i++) {
                int row = a_row + 32 * i;
                cp16(As_u + (s * 128 * P1_SA + row * P1_SA + a_c4 * 4) * 4,
                     x + (size_t)(mblk * 128 + row) * 1024 + (kt + 1) * 32 + a_c4 * 4);
                int k = b_k + 8 * i;
                cp16(Bs_u + (s * 32 * P1_SB + k * P1_SB + b_c4 * 4) * 4,
                     W + (size_t)((kt + 1) * 32 + k) * 1024 + hbase + b_c4 * 4);
            }
            asm volatile("cp.async.commit_group;\n");
        }

        const float* Ab = As + (kt & 1) * 128 * P1_SA;
        const float* Bb = Bs + (kt & 1) * 32 * P1_SB;

#pragma unroll
        for (int q = 0; q < 4; q++) {
            const int kk = q * 8;
            unsigned afr[4][4], bfr[4][2];
#pragma unroll
            for (int mt = 0; mt < 4; mt++) {
                int r = mi * 64 + mt * 16 + (lane >> 2);
                int c = kk + (lane & 3);
                afr[mt][0] = __float_as_uint(Ab[r * P1_SA + c]);
                afr[mt][1] = __float_as_uint(Ab[(r + 8) * P1_SA + c]);
                afr[mt][2] = __float_as_uint(Ab[r * P1_SA + c + 4]);
                afr[mt][3] = __float_as_uint(Ab[(r + 8) * P1_SA + c + 4]);
            }
#pragma unroll
            for (int nt = 0; nt < 4; nt++) {
                int nb = nj * 32 + nt * 8 + (lane >> 2);
                int kr = kk + (lane & 3);
                bfr[nt][0] = f2tf(Bb[kr * P1_SB + nb]);
                bfr[nt][1] = f2tf(Bb[(kr + 4) * P1_SB + nb]);
            }
#pragma unroll
            for (int mt = 0; mt < 4; mt++)
#pragma unroll
                for (int nt = 0; nt < 4; nt++)
                    mma8(acc[mt][nt], afr[mt], bfr[nt]);
        }
    }

    float* gbuf = g_gates + (size_t)gate * GATE_STRIDE;
#pragma unroll
    for (int mt = 0; mt < 4; mt++) {
#pragma unroll
        for (int nt = 0; nt < 4; nt++) {
#pragma unroll
            for (int rr = 0; rr < 2; rr++) {
                int m   = mblk * 128 + mi * 64 + mt * 16 + (lane >> 2) + rr * 8;
                int col = nj * 32 + nt * 8 + (lane & 3) * 2;
                int h   = hbase + col;
                int b   = m >> 9;
                int t   = m & 511;
                float2 o;
                o.x = acc[mt][nt][rr * 2 + 0] + __ldg(bias + h);
                o.y = acc[mt][nt][rr * 2 + 1] + __ldg(bias + h + 1);
                *(float2*)(gbuf + (size_t)t * 65536 + (size_t)b * 1024 + h) = o;
            }
        }
    }
}

// ---------------------------------------------------------------------------
// Phase 2: persistent recurrence, dataflow-synced. 16 warps = 2 m-halves x
// 8 K-groups; warp tile m32n32k128. FIXED: a-frag slot copied to locals
// before the q+4 prefetch overwrites it (r6 bug: (q+4)&3 == q&3).
// ---------------------------------------------------------------------------
#define P2_SW 40
#define P2_SZ 40
#define SMEM2_BYTES ((1024 * P2_SW + 4 * 64 * P2_SZ) * 4)

__global__ void __launch_bounds__(512, 1) lstm_rec(
    const float* __restrict__ Whi, const float* __restrict__ Whf,
    const float* __restrict__ Whc, const float* __restrict__ Who,
    float* __restrict__ out)
{
    extern __shared__ unsigned char smem_raw[];
    unsigned* Wsm  = (unsigned*)smem_raw;            // [1024][40]
    float*    zred = (float*)(Wsm + 1024 * P2_SW);   // [4][64][40]

    const int tid  = threadIdx.x;
    const int lane = tid & 31;
    const int w    = tid >> 5;
    const int wm   = w & 1;    // m-half: rows [wm*32, +32)
    const int kg   = w >> 1;   // K-group: k in [kg*128, +128)
    const int blk  = blockIdx.x;
    const int hb   = blk * 8;

    // weight slice -> SMEM (tf32), once
    {
        const float* Wg[4] = {Whi, Whf, Whc, Who};
        for (int idx = tid; idx < 4096; idx += 512) {
            int g = idx >> 10, k = idx & 1023;
            const float* src = Wg[g] + (size_t)k * 1024 + hb;
            float4 v0 = *(const float4*)(src);
            float4 v1 = *(const float4*)(src + 4);
            unsigned* d = &Wsm[k * P2_SW + g * 8];
            d[0] = f2tf(v0.x); d[1] = f2tf(v0.y); d[2] = f2tf(v0.z); d[3] = f2tf(v0.w);
            d[4] = f2tf(v1.x); d[5] = f2tf(v1.y); d[6] = f2tf(v1.z); d[7] = f2tf(v1.w);
        }
    }

    // a-frag layout: uint4 slot (kc, pmi, mt) at word (kc*4 + pmi*2 + mt)*128 + lane*4
    const int cbase = kg * 8192 + wm * 256 + lane * 4;   // + q*512 + mt*128

    // flag poll: warp kg's producers are CTAs [kg*16, +16), one per lane&15
    const unsigned* fp = g_flags + (kg * 16 + (lane & 15)) * 8;

    // elementwise coords + producer scatter index
    const int em = tid >> 3, ej = tid & 7;
    const int hcol = hb + ej;
    int p_widx;
    {
        int r = em, c = hcol;
        int kc = c >> 3, c7 = c & 7;
        int pmi = r >> 5, mt = (r >> 4) & 1, hi_r = (r >> 3) & 1, lr = r & 7;
        int hi_c = c7 >> 2, l2 = c7 & 3;
        p_widx = (kc * 4 + pmi * 2 + mt) * 128 + (lr * 4 + l2) * 4 + (hi_r + 2 * hi_c);
    }

    const int l3  = lane & 3;
    const int nbb = lane >> 2;
    float creg = 0.0f;           // c-state lives in a register

    __syncthreads();

#pragma unroll 1
    for (int t = 0; t < NT; ++t) {
        const unsigned* hA = g_hA[t & 1];
        unsigned*       hN = g_hA[(t + 1) & 1];

        // prefetch this step's gate preactivations (DRAM, hidden by GEMM)
        const size_t gidx = (size_t)t * 65536 + (size_t)em * 1024 + hcol;
        const float gi = __ldg(g_gates + gidx);
        const float gf = __ldg(g_gates + GATE_STRIDE + gidx);
        const float gc = __ldg(g_gates + 2u * GATE_STRIDE + gidx);
        const float go = __ldg(g_gates + 3u * GATE_STRIDE + gidx);

        // ---- forward wait: 16 producers of this warp's K range (acquire) ----
        for (;;) {
            unsigned v = ld_acq(fp);
            if (__all_sync(0xffffffffu, (int)v >= t)) break;
        }

        float acc[2][4][4];
#pragma unroll
        for (int a = 0; a < 2; a++)
#pragma unroll
            for (int b = 0; b < 4; b++)
#pragma unroll
                for (int c = 0; c < 4; c++) acc[a][b][c] = 0.0f;

        // a-frag pipeline, depth 4 (2 LDG.128 per q)
        uint4 abuf[4][2];
#pragma unroll
        for (int p = 0; p < 4; p++) {
            abuf[p][0] = __ldcg((const uint4*)(hA + cbase + p * 512));
            abuf[p][1] = __ldcg((const uint4*)(hA + cbase + p * 512 + 128));
        }

#pragma unroll
        for (int q = 0; q < 16; ++q) {
            // FIX: copy current slot to locals BEFORE overwriting it with q+4
            const uint4 av0 = abuf[q & 3][0];
            const uint4 av1 = abuf[q & 3][1];
            if (q + 4 < 16) {
                abuf[q & 3][0] = __ldcg((const uint4*)(hA + cbase + (q + 4) * 512));
                abuf[q & 3][1] = __ldcg((const uint4*)(hA + cbase + (q + 4) * 512 + 128));
            }

            const int kb = (kg * 16 + q) * 8 + l3;
            const unsigned* wrow = Wsm + kb * P2_SW;
            unsigned bfr[4][2];
#pragma unroll
            for (int nt = 0; nt < 4; nt++) {
                bfr[nt][0] = wrow[nt * 8 + nbb];
                bfr[nt][1] = wrow[4 * P2_SW + nt * 8 + nbb];
            }

            {
                unsigned afr0[4] = {av0.x, av0.y, av0.z, av0.w};
                unsigned afr1[4] = {av1.x, av1.y, av1.z, av1.w};
#pragma unroll
                for (int nt = 0; nt < 4; nt++) {
                    mma8(acc[0][nt], afr0, bfr[nt]);
                    mma8(acc[1][nt], afr1, bfr[nt]);
                }
            }
        }

        // ---- reduction: even K-groups store, odd RMW (2 phases, buf = kg>>1) ----
        float* z = zred + (kg >> 1) * 64 * P2_SZ;
        if (!(kg & 1)) {
#pragma unroll
            for (int mt = 0; mt < 2; mt++)
#pragma unroll
                for (int nt = 0; nt < 4; nt++)
#pragma unroll
                    for (int rr = 0; rr < 2; rr++) {
                        int r = wm * 32 + mt * 16 + (lane >> 2) + rr * 8;
                        int c = nt * 8 + (lane & 3) * 2;
                        *(float2*)&z[r * P2_SZ + c] =
                            make_float2(acc[mt][nt][rr * 2], acc[mt][nt][rr * 2 + 1]);
                    }
        }
        __syncthreads();   // sync A: phase-0 partials visible; all h(t) reads consumed

        // publish "h(t) consumed"; WAR-gate for overwriting h(t-1) buffer
        if (tid == 0)
            *(volatile unsigned*)&g_rd[blk * 8] = (unsigned)(t + 1);

        if (kg & 1) {
#pragma unroll
            for (int mt = 0; mt < 2; mt++)
#pragma unroll
                for (int nt = 0; nt < 4; nt++)
#pragma unroll
                    for (int rr = 0; rr < 2; rr++) {
                        int r = wm * 32 + mt * 16 + (lane >> 2) + rr * 8;
                        int c = nt * 8 + (lane & 3) * 2;
                        float2 old = *(float2*)&z[r * P2_SZ + c];
                        old.x += acc[mt][nt][rr * 2];
                        old.y += acc[mt][nt][rr * 2 + 1];
                        *(float2*)&z[r * P2_SZ + c] = old;
                    }
        }
        if (tid < GRID2) {
            while ((int)(*(volatile unsigned*)&g_rd[tid * 8]) < t) { }
        }
        __syncthreads();   // sync B

        // ---- elementwise LSTM cell update (1 element / thread) ----
        {
            const int zi_idx = em * P2_SZ + ej;
            const int ZB = 64 * P2_SZ;
            float zi = zred[zi_idx]           + zred[ZB + zi_idx]
                     + zred[2 * ZB + zi_idx]  + zred[3 * ZB + zi_idx] + gi;
            float zf = zred[zi_idx + 8]           + zred[ZB + zi_idx + 8]
                     + zred[2 * ZB + zi_idx + 8]  + zred[3 * ZB + zi_idx + 8] + gf;
            float zc = zred[zi_idx + 16]          + zred[ZB + zi_idx + 16]
                     + zred[2 * ZB + zi_idx + 16] + zred[3 * ZB + zi_idx + 16] + gc;
            float zo = zred[zi_idx + 24]          + zred[ZB + zi_idx + 24]
                     + zred[2 * ZB + zi_idx + 24] + zred[3 * ZB + zi_idx + 24] + go;
            float iv = sig_f(zi);
            float fv = sig_f(zf);
            float cv = tanh_f(zc);
            float ov = sig_f(zo);
            float cnew = fv * creg + iv * cv;
            creg = cnew;
            float hv = ov * tanh_f(cnew);
            hN[p_widx] = f2tf(hv);
            out[(size_t)em * 524288 + (size_t)t * 1024 + hcol] = hv;
            if (t == NT - 1) {
                out[33554432u + (size_t)em * 1024 + hcol] = hv;
                out[33554432u + 65536u + (size_t)em * 1024 + hcol] = cnew;
            }
        }

        // ---- release: h(t+1) of this CTA available ----
        __syncthreads();   // sync C
        if (tid == 0) {
            __threadfence();
            *(volatile unsigned*)&g_flags[blk * 8] = (unsigned)(t + 1);
        }
    }
}

// ---------------------------------------------------------------------------
extern "C" void kernel_launch(void* const* d_in, const int* in_sizes, int n_in,
                              void* d_out, int out_size)
{
    const float* x   = (const float*)d_in[0];
    const float* Wxi = (const float*)d_in[1];
    const float* Whi = (const float*)d_in[2];
    const float* bi  = (const float*)d_in[3];
    const float* Wxf = (const float*)d_in[4];
    const float* Whf = (const float*)d_in[5];
    const float* bf  = (const float*)d_in[6];
    const float* Wxc = (const float*)d_in[7];
    const float* Whc = (const float*)d_in[8];
    const float* bc  = (const float*)d_in[9];
    const float* Wxo = (const float*)d_in[10];
    const float* Who = (const float*)d_in[11];
    const float* bo  = (const float*)d_in[12];
    float* out = (float*)d_out;

    cudaFuncSetAttribute(lstm_xproj, cudaFuncAttributeMaxDynamicSharedMemorySize, P1_SMEM);
    cudaFuncSetAttribute(lstm_rec,   cudaFuncAttributeMaxDynamicSharedMemorySize, SMEM2_BYTES);

    dim3 g1(32, 256);
    lstm_xproj<<<g1, 256, P1_SMEM>>>(x, Wxi, Wxf, Wxc, Wxo, bi, bf, bc, bo);

    lstm_rec<<<GRID2, 512, SMEM2_BYTES>>>(Whi, Whf, Whc, Who, out);
}

// round 11
// speedup vs baseline: 1.5460x; 1.3200x over previous
#include <cuda_runtime.h>
#include <cuda_fp16.h>
#include <cstdint>
#include <cstddef>

#define NB 64
#define NT 512
#define NH 1024
#define GRID2 128

#define GATE_STRIDE 33554432u  // 512*64*1024

__device__ float    g_gates[4u * GATE_STRIDE];  // [gate][t][b][h]
__device__ unsigned g_hA[2][NB * NH / 2];       // h as fp16 pairs, MMA-fragment order
__device__ unsigned g_flags[GRID2 * 8];         // per-CTA "h(v) written" flags
__device__ unsigned g_rd[GRID2 * 8];            // per-CTA "h(v) consumed" flags

__device__ __forceinline__ unsigned f2tf(float f) {
    unsigned r;
    asm("cvt.rna.tf32.f32 %0, %1;" : "=r"(r) : "f"(f));
    return r;
}

__device__ __forceinline__ unsigned h2u(__half2 h) {
    unsigned u;
    __builtin_memcpy(&u, &h, 4);
    return u;
}

// tf32 m16n8k8 (phase 1)
__device__ __forceinline__ void mma8(float c[4], const unsigned a[4], const unsigned b[2]) {
    asm volatile(
        "mma.sync.aligned.m16n8k8.row.col.f32.tf32.tf32.f32 "
        "{%0,%1,%2,%3},{%4,%5,%6,%7},{%8,%9},{%0,%1,%2,%3};\n"
        : "+f"(c[0]), "+f"(c[1]), "+f"(c[2]), "+f"(c[3])
        : "r"(a[0]), "r"(a[1]), "r"(a[2]), "r"(a[3]), "r"(b[0]), "r"(b[1]));
}

// fp16 m16n8k16 (phase 2)
__device__ __forceinline__ void mma16(float c[4], const unsigned a[4], const unsigned b[2]) {
    asm volatile(
        "mma.sync.aligned.m16n8k16.row.col.f32.f16.f16.f32 "
        "{%0,%1,%2,%3},{%4,%5,%6,%7},{%8,%9},{%0,%1,%2,%3};\n"
        : "+f"(c[0]), "+f"(c[1]), "+f"(c[2]), "+f"(c[3])
        : "r"(a[0]), "r"(a[1]), "r"(a[2]), "r"(a[3]), "r"(b[0]), "r"(b[1]));
}

__device__ __forceinline__ void cp16(unsigned dst, const float* src) {
    asm volatile("cp.async.ca.shared.global [%0], [%1], 16;\n" :: "r"(dst), "l"(src));
}

__device__ __forceinline__ unsigned ld_acq(const unsigned* p) {
    unsigned v;
    asm volatile("ld.acquire.gpu.global.u32 %0, [%1];" : "=r"(v) : "l"(p) : "memory");
    return v;
}

__device__ __forceinline__ float sig_f(float z) {
    return __fdividef(1.0f, 1.0f + __expf(-z));
}
__device__ __forceinline__ float tanh_f(float z) {
    return __fdividef(2.0f, 1.0f + __expf(-2.0f * z)) - 1.0f;
}

// ---------------------------------------------------------------------------
// Phase 1: gate preactivations (unchanged — known good)
// ---------------------------------------------------------------------------
#define P1_SA 36
#define P1_SB 136
#define P1_SMEM ((2 * 128 * P1_SA + 2 * 32 * P1_SB) * 4)

__global__ void __launch_bounds__(256, 2) lstm_xproj(
    const float* __restrict__ x,
    const float* __restrict__ Wxi, const float* __restrict__ Wxf,
    const float* __restrict__ Wxc, const float* __restrict__ Wxo,
    const float* __restrict__ bi,  const float* __restrict__ bf,
    const float* __restrict__ bc,  const float* __restrict__ bo)
{
    extern __shared__ float p1s[];
    float* As = p1s;
    float* Bs = p1s + 2 * 128 * P1_SA;

    const int tid = threadIdx.x;

    if (blockIdx.x == 0 && blockIdx.y == 0) {
        uint4 z4 = make_uint4(0u, 0u, 0u, 0u);
        uint4* hb4 = (uint4*)g_hA[0];
#pragma unroll 4
        for (int i = tid; i < (NB * NH / 2) / 4; i += 256) hb4[i] = z4;
        for (int i = tid; i < GRID2 * 8; i += 256) { g_flags[i] = 0u; g_rd[i] = 0u; }
    }

    const int lane = tid & 31;
    const int w    = tid >> 5;
    const int mi   = w & 1;
    const int nj   = w >> 1;

    const int mblk  = blockIdx.y;
    const int nglob = blockIdx.x * 128;
    const int gate  = nglob >> 10;
    const int hbase = nglob & 1023;

    const float* W    = (gate == 0) ? Wxi : (gate == 1) ? Wxf : (gate == 2) ? Wxc : Wxo;
    const float* bias = (gate == 0) ? bi  : (gate == 1) ? bf  : (gate == 2) ? bc  : bo;

    const int a_row = tid >> 3, a_c4 = tid & 7;
    const int b_k   = tid >> 5, b_c4 = tid & 31;
    const unsigned As_u = (unsigned)__cvta_generic_to_shared(As);
    const unsigned Bs_u = (unsigned)__cvta_generic_to_shared(Bs);

    float acc[4][4][4];
#pragma unroll
    for (int a = 0; a < 4; a++)
#pragma unroll
        for (int b = 0; b < 4; b++)
#pragma unroll
            for (int c = 0; c < 4; c++) acc[a][b][c] = 0.0f;

    {
#pragma unroll
        for (int i = 0; i < 4; i++) {
            int row = a_row + 32 * i;
            cp16(As_u + (row * P1_SA + a_c4 * 4) * 4,
                 x + (size_t)(mblk * 128 + row) * 1024 + a_c4 * 4);
            int k = b_k + 8 * i;
            cp16(Bs_u + (k * P1_SB + b_c4 * 4) * 4,
                 W + (size_t)k * 1024 + hbase + b_c4 * 4);
        }
        asm volatile("cp.async.commit_group;\n");
    }

#pragma unroll 1
    for (int kt = 0; kt < 32; ++kt) {
        asm volatile("cp.async.wait_group 0;\n");
        __syncthreads();

        if (kt + 1 < 32) {
            int s = (kt + 1) & 1;
#pragma unroll
            for (int i = 0; i < 4; i++) {
                int row = a_row + 32 * i;
                cp16(As_u + (s * 128 * P1_SA + row * P1_SA + a_c4 * 4) * 4,
                     x + (size_t)(mblk * 128 + row) * 1024 + (kt + 1) * 32 + a_c4 * 4);
                int k = b_k + 8 * i;
                cp16(Bs_u + (s * 32 * P1_SB + k * P1_SB + b_c4 * 4) * 4,
                     W + (size_t)((kt + 1) * 32 + k) * 1024 + hbase + b_c4 * 4);
            }
            asm volatile("cp.async.commit_group;\n");
        }

        const float* Ab = As + (kt & 1) * 128 * P1_SA;
        const float* Bb = Bs + (kt & 1) * 32 * P1_SB;

#pragma unroll
        for (int q = 0; q < 4; q++) {
            const int kk = q * 8;
            unsigned afr[4][4], bfr[4][2];
#pragma unroll
            for (int mt = 0; mt < 4; mt++) {
                int r = mi * 64 + mt * 16 + (lane >> 2);
                int c = kk + (lane & 3);
                afr[mt][0] = __float_as_uint(Ab[r * P1_SA + c]);
                afr[mt][1] = __float_as_uint(Ab[(r + 8) * P1_SA + c]);
                afr[mt][2] = __float_as_uint(Ab[r * P1_SA + c + 4]);
                afr[mt][3] = __float_as_uint(Ab[(r + 8) * P1_SA + c + 4]);
            }
#pragma unroll
            for (int nt = 0; nt < 4; nt++) {
                int nb = nj * 32 + nt * 8 + (lane >> 2);
                int kr = kk + (lane & 3);
                bfr[nt][0] = f2tf(Bb[kr * P1_SB + nb]);
                bfr[nt][1] = f2tf(Bb[(kr + 4) * P1_SB + nb]);
            }
#pragma unroll
            for (int mt = 0; mt < 4; mt++)
#pragma unroll
                for (int nt = 0; nt < 4; nt++)
                    mma8(acc[mt][nt], afr[mt], bfr[nt]);
        }
    }

    float* gbuf = g_gates + (size_t)gate * GATE_STRIDE;
#pragma unroll
    for (int mt = 0; mt < 4; mt++) {
#pragma unroll
        for (int nt = 0; nt < 4; nt++) {
#pragma unroll
            for (int rr = 0; rr < 2; rr++) {
                int m   = mblk * 128 + mi * 64 + mt * 16 + (lane >> 2) + rr * 8;
                int col = nj * 32 + nt * 8 + (lane & 3) * 2;
                int h   = hbase + col;
                int b   = m >> 9;
                int t   = m & 511;
                float2 o;
                o.x = acc[mt][nt][rr * 2 + 0] + __ldg(bias + h);
                o.y = acc[mt][nt][rr * 2 + 1] + __ldg(bias + h + 1);
                *(float2*)(gbuf + (size_t)t * 65536 + (size_t)b * 1024 + h) = o;
            }
        }
    }
}

// ---------------------------------------------------------------------------
// Phase 2: persistent recurrence, fp16 MMA (m16n8k16), dataflow-synced.
// 128 CTAs x 512 thr; CTA owns h-cols [blk*8,+8) x 4 gates (N=32).
// 16 warps = 2 m-halves x 8 K-groups (k128/warp). h state = packed half2
// fragments in global (16 MB/step L2 broadcast). W_h in SMEM as k-paired
// half2 (conflict-free, stride 40).
// FIX vs r10: b-fragment k2 row index includes the warp's K-group offset
// (kg*64 + ...), matching the a-fragment side.
// ---------------------------------------------------------------------------
#define P2_SW 40
#define P2_SZ 40
#define SMEM2_BYTES ((512 * P2_SW + 4 * 64 * P2_SZ) * 4)

__global__ void __launch_bounds__(512, 1) lstm_rec(
    const float* __restrict__ Whi, const float* __restrict__ Whf,
    const float* __restrict__ Whc, const float* __restrict__ Who,
    float* __restrict__ out)
{
    extern __shared__ unsigned char smem_raw[];
    unsigned* Wsm  = (unsigned*)smem_raw;            // [512][40]  half2 words, k-paired
    float*    zred = (float*)(Wsm + 512 * P2_SW);    // [4][64][40]

    const int tid  = threadIdx.x;
    const int lane = tid & 31;
    const int w    = tid >> 5;
    const int wm   = w & 1;    // m-half: rows [wm*32, +32)
    const int kg   = w >> 1;   // K-group: k in [kg*128, +128)
    const int blk  = blockIdx.x;
    const int hb   = blk * 8;

    // weight slice -> SMEM as half2 (k, k+1) pairs, once
    {
        const float* Wg[4] = {Whi, Whf, Whc, Who};
        for (int idx = tid; idx < 2048; idx += 512) {     // 4 gates x 512 k2
            int g = idx >> 9, k2 = idx & 511;
            const float* s0 = Wg[g] + (size_t)(2 * k2) * 1024 + hb;
            const float* s1 = s0 + 1024;
            float4 a0 = *(const float4*)(s0);
            float4 a1 = *(const float4*)(s0 + 4);
            float4 b0 = *(const float4*)(s1);
            float4 b1 = *(const float4*)(s1 + 4);
            unsigned* d = &Wsm[k2 * P2_SW + g * 8];
            d[0] = h2u(__floats2half2_rn(a0.x, b0.x));
            d[1] = h2u(__floats2half2_rn(a0.y, b0.y));
            d[2] = h2u(__floats2half2_rn(a0.z, b0.z));
            d[3] = h2u(__floats2half2_rn(a0.w, b0.w));
            d[4] = h2u(__floats2half2_rn(a1.x, b1.x));
            d[5] = h2u(__floats2half2_rn(a1.y, b1.y));
            d[6] = h2u(__floats2half2_rn(a1.z, b1.z));
            d[7] = h2u(__floats2half2_rn(a1.w, b1.w));
        }
    }

    // a-frag layout (half2 words): word = ((kg*8+q)*4 + wm*2 + mt)*128 + lane*4 + j
    const int cbase = kg * 4096 + wm * 256 + lane * 4;   // + q*512 + mt*128

    // flag poll: warp kg's producers are CTAs [kg*16, +16)
    const unsigned* fp = g_flags + (kg * 16 + (lane & 15)) * 8;

    // elementwise coords + producer half-scatter index
    const int em = tid >> 3, ej = tid & 7;
    const int hcol = hb + ej;
    int p_hidx;   // index in halves
    {
        int r = em, c = hcol;
        int pkg = c >> 7, c7 = c & 127;
        int pq = c7 >> 4, k16 = c7 & 15;
        int pwm = r >> 5, pmt = (r >> 4) & 1, hi_r = (r >> 3) & 1, lr = r & 7;
        int hi_k = k16 >> 3, l3k = (k16 >> 1) & 3;
        int word = ((pkg * 8 + pq) * 4 + pwm * 2 + pmt) * 128
                 + (lr * 4 + l3k) * 4 + (hi_r + 2 * hi_k);
        p_hidx = word * 2 + (k16 & 1);
    }

    const int l3  = lane & 3;
    const int nbb = lane >> 2;
    float creg = 0.0f;

    __syncthreads();

#pragma unroll 1
    for (int t = 0; t < NT; ++t) {
        const unsigned* hA = g_hA[t & 1];
        __half*         hN = (__half*)g_hA[(t + 1) & 1];

        // prefetch this step's gate preactivations
        const size_t gidx = (size_t)t * 65536 + (size_t)em * 1024 + hcol;
        const float gi = __ldg(g_gates + gidx);
        const float gf = __ldg(g_gates + GATE_STRIDE + gidx);
        const float gc = __ldg(g_gates + 2u * GATE_STRIDE + gidx);
        const float go = __ldg(g_gates + 3u * GATE_STRIDE + gidx);

        // ---- forward wait: 16 producers of this warp's K range ----
        for (;;) {
            unsigned v = ld_acq(fp);
            if (__all_sync(0xffffffffu, (int)v >= t)) break;
        }

        float acc[2][4][4];
#pragma unroll
        for (int a = 0; a < 2; a++)
#pragma unroll
            for (int b = 0; b < 4; b++)
#pragma unroll
                for (int c = 0; c < 4; c++) acc[a][b][c] = 0.0f;

        // a-frag pipeline, depth 4 over 8 q-steps (2 LDG.128 per q)
        uint4 abuf[4][2];
#pragma unroll
        for (int p = 0; p < 4; p++) {
            abuf[p][0] = __ldcg((const uint4*)(hA + cbase + p * 512));
            abuf[p][1] = __ldcg((const uint4*)(hA + cbase + p * 512 + 128));
        }

#pragma unroll
        for (int q = 0; q < 8; ++q) {
            // copy current slot before overwriting with q+4
            const uint4 av0 = abuf[q & 3][0];
            const uint4 av1 = abuf[q & 3][1];
            if (q + 4 < 8) {
                abuf[q & 3][0] = __ldcg((const uint4*)(hA + cbase + (q + 4) * 512));
                abuf[q & 3][1] = __ldcg((const uint4*)(hA + cbase + (q + 4) * 512 + 128));
            }

            // b-fragments: k2 rows kg*64 + q*8 + l3 (b0) and +4 (b1)  [FIXED: kg offset]
            const unsigned* wr0 = Wsm + (kg * 64 + q * 8 + l3) * P2_SW;
            const unsigned* wr1 = Wsm + (kg * 64 + q * 8 + 4 + l3) * P2_SW;
            unsigned bfr[4][2];
#pragma unroll
            for (int nt = 0; nt < 4; nt++) {
                bfr[nt][0] = wr0[nt * 8 + nbb];
                bfr[nt][1] = wr1[nt * 8 + nbb];
            }

            {
                unsigned afr0[4] = {av0.x, av0.y, av0.z, av0.w};
                unsigned afr1[4] = {av1.x, av1.y, av1.z, av1.w};
#pragma unroll
                for (int nt = 0; nt < 4; nt++) {
                    mma16(acc[0][nt], afr0, bfr[nt]);
                    mma16(acc[1][nt], afr1, bfr[nt]);
                }
            }
        }

        // ---- reduction: even K-groups store, odd RMW (buf = kg>>1) ----
        float* z = zred + (kg >> 1) * 64 * P2_SZ;
        if (!(kg & 1)) {
#pragma unroll
            for (int mt = 0; mt < 2; mt++)
#pragma unroll
                for (int nt = 0; nt < 4; nt++)
#pragma unroll
                    for (int rr = 0; rr < 2; rr++) {
                        int r = wm * 32 + mt * 16 + (lane >> 2) + rr * 8;
                        int c = nt * 8 + (lane & 3) * 2;
                        *(float2*)&z[r * P2_SZ + c] =
                            make_float2(acc[mt][nt][rr * 2], acc[mt][nt][rr * 2 + 1]);
                    }
        }
        __syncthreads();   // sync A

        if (tid == 0)
            *(volatile unsigned*)&g_rd[blk * 8] = (unsigned)(t + 1);

        if (kg & 1) {
#pragma unroll
            for (int mt = 0; mt < 2; mt++)
#pragma unroll
                for (int nt = 0; nt < 4; nt++)
#pragma unroll
                    for (int rr = 0; rr < 2; rr++) {
                        int r = wm * 32 + mt * 16 + (lane >> 2) + rr * 8;
                        int c = nt * 8 + (lane & 3) * 2;
                        float2 old = *(float2*)&z[r * P2_SZ + c];
                        old.x += acc[mt][nt][rr * 2];
                        old.y += acc[mt][nt][rr * 2 + 1];
                        *(float2*)&z[r * P2_SZ + c] = old;
                    }
        }
        if (tid < GRID2) {
            while ((int)(*(volatile unsigned*)&g_rd[tid * 8]) < t) { }
        }
        __syncthreads();   // sync B

        // ---- elementwise LSTM cell update ----
        {
            const int zi_idx = em * P2_SZ + ej;
            const int ZB = 64 * P2_SZ;
            float zi = zred[zi_idx]           + zred[ZB + zi_idx]
                     + zred[2 * ZB + zi_idx]  + zred[3 * ZB + zi_idx] + gi;
            float zf = zred[zi_idx + 8]           + zred[ZB + zi_idx + 8]
                     + zred[2 * ZB + zi_idx + 8]  + zred[3 * ZB + zi_idx + 8] + gf;
            float zc = zred[zi_idx + 16]          + zred[ZB + zi_idx + 16]
                     + zred[2 * ZB + zi_idx + 16] + zred[3 * ZB + zi_idx + 16] + gc;
            float zo = zred[zi_idx + 24]          + zred[ZB + zi_idx + 24]
                     + zred[2 * ZB + zi_idx + 24] + zred[3 * ZB + zi_idx + 24] + go;
            float iv = sig_f(zi);
            float fv = sig_f(zf);
            float cv = tanh_f(zc);
            float ov = sig_f(zo);
            float cnew = fv * creg + iv * cv;
            creg = cnew;
            float hv = ov * tanh_f(cnew);
            hN[p_hidx] = __float2half_rn(hv);
            out[(size_t)em * 524288 + (size_t)t * 1024 + hcol] = hv;
            if (t == NT - 1) {
                out[33554432u + (size_t)em * 1024 + hcol] = hv;
                out[33554432u + 65536u + (size_t)em * 1024 + hcol] = cnew;
            }
        }

        // ---- release: h(t+1) of this CTA available ----
        __syncthreads();   // sync C
        if (tid == 0) {
            __threadfence();
            *(volatile unsigned*)&g_flags[blk * 8] = (unsigned)(t + 1);
        }
    }
}

// ---------------------------------------------------------------------------
extern "C" void kernel_launch(void* const* d_in, const int* in_sizes, int n_in,
                              void* d_out, int out_size)
{
    const float* x   = (const float*)d_in[0];
    const float* Wxi = (const float*)d_in[1];
    const float* Whi = (const float*)d_in[2];
    const float* bi  = (const float*)d_in[3];
    const float* Wxf = (const float*)d_in[4];
    const float* Whf = (const float*)d_in[5];
    const float* bf  = (const float*)d_in[6];
    const float* Wxc = (const float*)d_in[7];
    const float* Whc = (const float*)d_in[8];
    const float* bc  = (const float*)d_in[9];
    const float* Wxo = (const float*)d_in[10];
    const float* Who = (const float*)d_in[11];
    const float* bo  = (const float*)d_in[12];
    float* out = (float*)d_out;

    cudaFuncSetAttribute(lstm_xproj, cudaFuncAttributeMaxDynamicSharedMemorySize, P1_SMEM);
    cudaFuncSetAttribute(lstm_rec,   cudaFuncAttributeMaxDynamicSharedMemorySize, SMEM2_BYTES);

    dim3 g1(32, 256);
    lstm_xproj<<<g1, 256, P1_SMEM>>>(x, Wxi, Wxf, Wxc, Wxo, bi, bf, bc, bo);

    lstm_rec<<<GRID2, 512, SMEM2_BYTES>>>(Whi, Whf, Whc, Who, out);
}

// round 12
// speedup vs baseline: 1.7987x; 1.1635x over previous
#include <cuda_runtime.h>
#include <cuda_fp16.h>
#include <cstdint>
#include <cstddef>

#define NB 64
#define NT 512
#define NH 1024
#define GRID2 128

#define GATE_STRIDE 33554432u  // 512*64*1024

__device__ float    g_gates[4u * GATE_STRIDE];  // [gate][t][b][h]
__device__ unsigned g_hA[2][NB * NH / 2];       // h as fp16 pairs, MMA-fragment order
__device__ unsigned g_flags[GRID2 * 8];         // per-CTA "h(v) written" flags
__device__ unsigned g_rd[GRID2 * 8];            // per-CTA "h(v) consumed" flags
__device__ unsigned g_xh[16777216];             // x as half2 (33.5M halves, row-major)
__device__ unsigned g_Wh[2097152];              // W_x as half2 k-pairs: [gate][k2:512][n:1024]

__device__ __forceinline__ unsigned h2u(__half2 h) {
    unsigned u;
    __builtin_memcpy(&u, &h, 4);
    return u;
}

// fp16 m16n8k16
__device__ __forceinline__ void mma16(float c[4], const unsigned a[4], const unsigned b[2]) {
    asm volatile(
        "mma.sync.aligned.m16n8k16.row.col.f32.f16.f16.f32 "
        "{%0,%1,%2,%3},{%4,%5,%6,%7},{%8,%9},{%0,%1,%2,%3};\n"
        : "+f"(c[0]), "+f"(c[1]), "+f"(c[2]), "+f"(c[3])
        : "r"(a[0]), "r"(a[1]), "r"(a[2]), "r"(a[3]), "r"(b[0]), "r"(b[1]));
}

__device__ __forceinline__ void cp16(unsigned dst, const void* src) {
    asm volatile("cp.async.ca.shared.global [%0], [%1], 16;\n" :: "r"(dst), "l"(src));
}

__device__ __forceinline__ unsigned ld_acq(const unsigned* p) {
    unsigned v;
    asm volatile("ld.acquire.gpu.global.u32 %0, [%1];" : "=r"(v) : "l"(p) : "memory");
    return v;
}

__device__ __forceinline__ float sig_f(float z) {
    return __fdividef(1.0f, 1.0f + __expf(-z));
}
__device__ __forceinline__ float tanh_f(float z) {
    return __fdividef(2.0f, 1.0f + __expf(-2.0f * z)) - 1.0f;
}

// ---------------------------------------------------------------------------
// Phase 0: convert x and W_x to fp16 scratch; per-replay init.
// x  -> g_xh   half2 along k (row-major [m][k2])
// Wx -> g_Wh   half2 of (k, k+1): [gate][k2][n]
// ---------------------------------------------------------------------------
__global__ void __launch_bounds__(256) lstm_conv(
    const float* __restrict__ x,
    const float* __restrict__ Wxi, const float* __restrict__ Wxf,
    const float* __restrict__ Wxc, const float* __restrict__ Wxo)
{
    const int tid    = blockIdx.x * blockDim.x + threadIdx.x;
    const int stride = gridDim.x * blockDim.x;

    // x: 16.7M float2 -> half2
    const float2* x2 = (const float2*)x;
#pragma unroll 4
    for (int i = tid; i < 16777216; i += stride) {
        float2 v = x2[i];
        g_xh[i] = h2u(__floats2half2_rn(v.x, v.y));
    }

    // W: [gate][k2][n]  <- (W[2k2][n], W[2k2+1][n])
    for (int i = tid; i < 2097152; i += stride) {
        int g  = i >> 19;
        int r  = i & 524287;
        int k2 = r >> 10;
        int n  = r & 1023;
        const float* W = (g == 0) ? Wxi : (g == 1) ? Wxf : (g == 2) ? Wxc : Wxo;
        float lo = W[(size_t)(2 * k2) * 1024 + n];
        float hi = W[(size_t)(2 * k2 + 1) * 1024 + n];
        g_Wh[i] = h2u(__floats2half2_rn(lo, hi));
    }

    // per-replay init: h0 fragments = 0, flags = 0
    if (tid < (NB * NH / 2) / 4) {
        ((uint4*)g_hA[0])[tid] = make_uint4(0u, 0u, 0u, 0u);
    }
    if (tid < GRID2 * 8) { g_flags[tid] = 0u; g_rd[tid] = 0u; }
}

// ---------------------------------------------------------------------------
// Phase 1: gate preactivations, fp16 MMA (m16n8k16).
// M=32768, N=4096 (4 gates x 1024), K=1024, k64 per iter (16 iters).
// Block 128x128, 256 thr, warp tile m64n32. cp.async double-buffered.
// A smem: [2][128][36] u32 (half2 along k). B smem: [2][32][136] u32
// (half2 k-pairs, n along row). fp32 accum + fp32 bias epilogue.
// ---------------------------------------------------------------------------
#define P1_SA 36
#define P1_SB 136
#define P1_SMEM ((2 * 128 * P1_SA + 2 * 32 * P1_SB) * 4)

__global__ void __launch_bounds__(256, 2) lstm_xproj(
    const float* __restrict__ bi, const float* __restrict__ bf,
    const float* __restrict__ bc, const float* __restrict__ bo)
{
    extern __shared__ unsigned p1s[];
    unsigned* As = p1s;                        // [2][128][P1_SA]
    unsigned* Bs = p1s + 2 * 128 * P1_SA;      // [2][32][P1_SB]

    const int tid  = threadIdx.x;
    const int lane = tid & 31;
    const int w    = tid >> 5;
    const int mi   = w & 1;   // m base = mi*64
    const int nj   = w >> 1;  // n base = nj*32

    const int mblk  = blockIdx.y;
    const int nglob = blockIdx.x * 128;
    const int gate  = nglob >> 10;
    const int hbase = nglob & 1023;

    const float* bias = (gate == 0) ? bi : (gate == 1) ? bf : (gate == 2) ? bc : bo;

    // copy coords: A: 1024 cp16 (row, 8 segs of 4 words); B: 1024 cp16 (32 k2-rows, 32 segs)
    const int a_row = tid >> 3, a_seg = tid & 7;     // +32 rows per i
    const int b_k2  = tid >> 5, b_seg = tid & 31;    // +8 rows per i
    const unsigned As_u = (unsigned)__cvta_generic_to_shared(As);
    const unsigned Bs_u = (unsigned)__cvta_generic_to_shared(Bs);

    const unsigned* Wg = g_Wh + gate * 524288;

    float acc[4][4][4];
#pragma unroll
    for (int a = 0; a < 4; a++)
#pragma unroll
        for (int b = 0; b < 4; b++)
#pragma unroll
            for (int c = 0; c < 4; c++) acc[a][b][c] = 0.0f;

    // prefetch tile 0
    {
#pragma unroll
        for (int i = 0; i < 4; i++) {
            int row = a_row + 32 * i;
            cp16(As_u + (row * P1_SA + a_seg * 4) * 4,
                 g_xh + (size_t)(mblk * 128 + row) * 512 + a_seg * 4);
            int k2 = b_k2 + 8 * i;
            cp16(Bs_u + (k2 * P1_SB + b_seg * 4) * 4,
                 Wg + (size_t)k2 * 1024 + hbase + b_seg * 4);
        }
        asm volatile("cp.async.commit_group;\n");
    }

#pragma unroll 1
    for (int kt = 0; kt < 16; ++kt) {
        asm volatile("cp.async.wait_group 0;\n");
        __syncthreads();

        if (kt + 1 < 16) {
            int s = (kt + 1) & 1;
#pragma unroll
            for (int i = 0; i < 4; i++) {
                int row = a_row + 32 * i;
                cp16(As_u + (s * 128 * P1_SA + row * P1_SA + a_seg * 4) * 4,
                     g_xh + (size_t)(mblk * 128 + row) * 512 + (kt + 1) * 32 + a_seg * 4);
                int k2 = b_k2 + 8 * i;
                cp16(Bs_u + (s * 32 * P1_SB + k2 * P1_SB + b_seg * 4) * 4,
                     Wg + (size_t)((kt + 1) * 32 + k2) * 1024 + hbase + b_seg * 4);
            }
            asm volatile("cp.async.commit_group;\n");
        }

        const unsigned* Ab = As + (kt & 1) * 128 * P1_SA;
        const unsigned* Bb = Bs + (kt & 1) * 32 * P1_SB;

#pragma unroll
        for (int q = 0; q < 4; q++) {
            unsigned afr[4][4], bfr[4][2];
#pragma unroll
            for (int mt = 0; mt < 4; mt++) {
                int r = mi * 64 + mt * 16 + (lane >> 2);
                int cw = q * 8 + (lane & 3);
                afr[mt][0] = Ab[r * P1_SA + cw];
                afr[mt][1] = Ab[(r + 8) * P1_SA + cw];
                afr[mt][2] = Ab[r * P1_SA + cw + 4];
                afr[mt][3] = Ab[(r + 8) * P1_SA + cw + 4];
            }
#pragma unroll
            for (int nt = 0; nt < 4; nt++) {
                int nb = nj * 32 + nt * 8 + (lane >> 2);
                bfr[nt][0] = Bb[(q * 8 + (lane & 3)) * P1_SB + nb];
                bfr[nt][1] = Bb[(q * 8 + 4 + (lane & 3)) * P1_SB + nb];
            }
#pragma unroll
            for (int mt = 0; mt < 4; mt++)
#pragma unroll
                for (int nt = 0; nt < 4; nt++)
                    mma16(acc[mt][nt], afr[mt], bfr[nt]);
        }
    }

    float* gbuf = g_gates + (size_t)gate * GATE_STRIDE;
#pragma unroll
    for (int mt = 0; mt < 4; mt++) {
#pragma unroll
        for (int nt = 0; nt < 4; nt++) {
#pragma unroll
            for (int rr = 0; rr < 2; rr++) {
                int m   = mblk * 128 + mi * 64 + mt * 16 + (lane >> 2) + rr * 8;
                int col = nj * 32 + nt * 8 + (lane & 3) * 2;
                int h   = hbase + col;
                int b   = m >> 9;
                int t   = m & 511;
                float2 o;
                o.x = acc[mt][nt][rr * 2 + 0] + __ldg(bias + h);
                o.y = acc[mt][nt][rr * 2 + 1] + __ldg(bias + h + 1);
                *(float2*)(gbuf + (size_t)t * 65536 + (size_t)b * 1024 + h) = o;
            }
        }
    }
}

// ---------------------------------------------------------------------------
// Phase 2: persistent recurrence, fp16 MMA (m16n8k16), dataflow-synced.
// (byte-identical to round 11 — known good)
// ---------------------------------------------------------------------------
#define P2_SW 40
#define P2_SZ 40
#define SMEM2_BYTES ((512 * P2_SW + 4 * 64 * P2_SZ) * 4)

__global__ void __launch_bounds__(512, 1) lstm_rec(
    const float* __restrict__ Whi, const float* __restrict__ Whf,
    const float* __restrict__ Whc, const float* __restrict__ Who,
    float* __restrict__ out)
{
    extern __shared__ unsigned char smem_raw[];
    unsigned* Wsm  = (unsigned*)smem_raw;            // [512][40]  half2 words, k-paired
    float*    zred = (float*)(Wsm + 512 * P2_SW);    // [4][64][40]

    const int tid  = threadIdx.x;
    const int lane = tid & 31;
    const int w    = tid >> 5;
    const int wm   = w & 1;    // m-half: rows [wm*32, +32)
    const int kg   = w >> 1;   // K-group: k in [kg*128, +128)
    const int blk  = blockIdx.x;
    const int hb   = blk * 8;

    // weight slice -> SMEM as half2 (k, k+1) pairs, once
    {
        const float* Wg[4] = {Whi, Whf, Whc, Who};
        for (int idx = tid; idx < 2048; idx += 512) {     // 4 gates x 512 k2
            int g = idx >> 9, k2 = idx & 511;
            const float* s0 = Wg[g] + (size_t)(2 * k2) * 1024 + hb;
            const float* s1 = s0 + 1024;
            float4 a0 = *(const float4*)(s0);
            float4 a1 = *(const float4*)(s0 + 4);
            float4 b0 = *(const float4*)(s1);
            float4 b1 = *(const float4*)(s1 + 4);
            unsigned* d = &Wsm[k2 * P2_SW + g * 8];
            d[0] = h2u(__floats2half2_rn(a0.x, b0.x));
            d[1] = h2u(__floats2half2_rn(a0.y, b0.y));
            d[2] = h2u(__floats2half2_rn(a0.z, b0.z));
            d[3] = h2u(__floats2half2_rn(a0.w, b0.w));
            d[4] = h2u(__floats2half2_rn(a1.x, b1.x));
            d[5] = h2u(__floats2half2_rn(a1.y, b1.y));
            d[6] = h2u(__floats2half2_rn(a1.z, b1.z));
            d[7] = h2u(__floats2half2_rn(a1.w, b1.w));
        }
    }

    // a-frag layout (half2 words): word = ((kg*8+q)*4 + wm*2 + mt)*128 + lane*4 + j
    const int cbase = kg * 4096 + wm * 256 + lane * 4;   // + q*512 + mt*128

    // flag poll: warp kg's producers are CTAs [kg*16, +16)
    const unsigned* fp = g_flags + (kg * 16 + (lane & 15)) * 8;

    // elementwise coords + producer half-scatter index
    const int em = tid >> 3, ej = tid & 7;
    const int hcol = hb + ej;
    int p_hidx;   // index in halves
    {
        int r = em, c = hcol;
        int pkg = c >> 7, c7 = c & 127;
        int pq = c7 >> 4, k16 = c7 & 15;
        int pwm = r >> 5, pmt = (r >> 4) & 1, hi_r = (r >> 3) & 1, lr = r & 7;
        int hi_k = k16 >> 3, l3k = (k16 >> 1) & 3;
        int word = ((pkg * 8 + pq) * 4 + pwm * 2 + pmt) * 128
                 + (lr * 4 + l3k) * 4 + (hi_r + 2 * hi_k);
        p_hidx = word * 2 + (k16 & 1);
    }

    const int l3  = lane & 3;
    const int nbb = lane >> 2;
    float creg = 0.0f;

    __syncthreads();

#pragma unroll 1
    for (int t = 0; t < NT; ++t) {
        const unsigned* hA = g_hA[t & 1];
        __half*         hN = (__half*)g_hA[(t + 1) & 1];

        // prefetch this step's gate preactivations
        const size_t gidx = (size_t)t * 65536 + (size_t)em * 1024 + hcol;
        const float gi = __ldg(g_gates + gidx);
        const float gf = __ldg(g_gates + GATE_STRIDE + gidx);
        const float gc = __ldg(g_gates + 2u * GATE_STRIDE + gidx);
        const float go = __ldg(g_gates + 3u * GATE_STRIDE + gidx);

        // ---- forward wait: 16 producers of this warp's K range ----
        for (;;) {
            unsigned v = ld_acq(fp);
            if (__all_sync(0xffffffffu, (int)v >= t)) break;
        }

        float acc[2][4][4];
#pragma unroll
        for (int a = 0; a < 2; a++)
#pragma unroll
            for (int b = 0; b < 4; b++)
#pragma unroll
                for (int c = 0; c < 4; c++) acc[a][b][c] = 0.0f;

        // a-frag pipeline, depth 4 over 8 q-steps (2 LDG.128 per q)
        uint4 abuf[4][2];
#pragma unroll
        for (int p = 0; p < 4; p++) {
            abuf[p][0] = __ldcg((const uint4*)(hA + cbase + p * 512));
            abuf[p][1] = __ldcg((const uint4*)(hA + cbase + p * 512 + 128));
        }

#pragma unroll
        for (int q = 0; q < 8; ++q) {
            // copy current slot before overwriting with q+4
            const uint4 av0 = abuf[q & 3][0];
            const uint4 av1 = abuf[q & 3][1];
            if (q + 4 < 8) {
                abuf[q & 3][0] = __ldcg((const uint4*)(hA + cbase + (q + 4) * 512));
                abuf[q & 3][1] = __ldcg((const uint4*)(hA + cbase + (q + 4) * 512 + 128));
            }

            // b-fragments: k2 rows kg*64 + q*8 + l3 (b0) and +4 (b1)
            const unsigned* wr0 = Wsm + (kg * 64 + q * 8 + l3) * P2_SW;
            const unsigned* wr1 = Wsm + (kg * 64 + q * 8 + 4 + l3) * P2_SW;
            unsigned bfr[4][2];
#pragma unroll
            for (int nt = 0; nt < 4; nt++) {
                bfr[nt][0] = wr0[nt * 8 + nbb];
                bfr[nt][1] = wr1[nt * 8 + nbb];
            }

            {
                unsigned afr0[4] = {av0.x, av0.y, av0.z, av0.w};
                unsigned afr1[4] = {av1.x, av1.y, av1.z, av1.w};
#pragma unroll
                for (int nt = 0; nt < 4; nt++) {
                    mma16(acc[0][nt], afr0, bfr[nt]);
                    mma16(acc[1][nt], afr1, bfr[nt]);
                }
            }
        }

        // ---- reduction: even K-groups store, odd RMW (buf = kg>>1) ----
        float* z = zred + (kg >> 1) * 64 * P2_SZ;
        if (!(kg & 1)) {
#pragma unroll
            for (int mt = 0; mt < 2; mt++)
#pragma unroll
                for (int nt = 0; nt < 4; nt++)
#pragma unroll
                    for (int rr = 0; rr < 2; rr++) {
                        int r = wm * 32 + mt * 16 + (lane >> 2) + rr * 8;
                        int c = nt * 8 + (lane & 3) * 2;
                        *(float2*)&z[r * P2_SZ + c] =
                            make_float2(acc[mt][nt][rr * 2], acc[mt][nt][rr * 2 + 1]);
                    }
        }
        __syncthreads();   // sync A

        if (tid == 0)
            *(volatile unsigned*)&g_rd[blk * 8] = (unsigned)(t + 1);

        if (kg & 1) {
#pragma unroll
            for (int mt = 0; mt < 2; mt++)
#pragma unroll
                for (int nt = 0; nt < 4; nt++)
#pragma unroll
                    for (int rr = 0; rr < 2; rr++) {
                        int r = wm * 32 + mt * 16 + (lane >> 2) + rr * 8;
                        int c = nt * 8 + (lane & 3) * 2;
                        float2 old = *(float2*)&z[r * P2_SZ + c];
                        old.x += acc[mt][nt][rr * 2];
                        old.y += acc[mt][nt][rr * 2 + 1];
                        *(float2*)&z[r * P2_SZ + c] = old;
                    }
        }
        if (tid < GRID2) {
            while ((int)(*(volatile unsigned*)&g_rd[tid * 8]) < t) { }
        }
        __syncthreads();   // sync B

        // ---- elementwise LSTM cell update ----
        {
            const int zi_idx = em * P2_SZ + ej;
            const int ZB = 64 * P2_SZ;
            float zi = zred[zi_idx]           + zred[ZB + zi_idx]
                     + zred[2 * ZB + zi_idx]  + zred[3 * ZB + zi_idx] + gi;
            float zf = zred[zi_idx + 8]           + zred[ZB + zi_idx + 8]
                     + zred[2 * ZB + zi_idx + 8]  + zred[3 * ZB + zi_idx + 8] + gf;
            float zc = zred[zi_idx + 16]          + zred[ZB + zi_idx + 16]
                     + zred[2 * ZB + zi_idx + 16] + zred[3 * ZB + zi_idx + 16] + gc;
            float zo = zred[zi_idx + 24]          + zred[ZB + zi_idx + 24]
                     + zred[2 * ZB + zi_idx + 24] + zred[3 * ZB + zi_idx + 24] + go;
            float iv = sig_f(zi);
            float fv = sig_f(zf);
            float cv = tanh_f(zc);
            float ov = sig_f(zo);
            float cnew = fv * creg + iv * cv;
            creg = cnew;
            float hv = ov * tanh_f(cnew);
            hN[p_hidx] = __float2half_rn(hv);
            out[(size_t)em * 524288 + (size_t)t * 1024 + hcol] = hv;
            if (t == NT - 1) {
                out[33554432u + (size_t)em * 1024 + hcol] = hv;
                out[33554432u + 65536u + (size_t)em * 1024 + hcol] = cnew;
            }
        }

        // ---- release: h(t+1) of this CTA available ----
        __syncthreads();   // sync C
        if (tid == 0) {
            __threadfence();
            *(volatile unsigned*)&g_flags[blk * 8] = (unsigned)(t + 1);
        }
    }
}

// ---------------------------------------------------------------------------
extern "C" void kernel_launch(void* const* d_in, const int* in_sizes, int n_in,
                              void* d_out, int out_size)
{
    const float* x   = (const float*)d_in[0];
    const float* Wxi = (const float*)d_in[1];
    const float* Whi = (const float*)d_in[2];
    const float* bi  = (const float*)d_in[3];
    const float* Wxf = (const float*)d_in[4];
    const float* Whf = (const float*)d_in[5];
    const float* bf  = (const float*)d_in[6];
    const float* Wxc = (const float*)d_in[7];
    const float* Whc = (const float*)d_in[8];
    const float* bc  = (const float*)d_in[9];
    const float* Wxo = (const float*)d_in[10];
    const float* Who = (const float*)d_in[11];
    const float* bo  = (const float*)d_in[12];
    float* out = (float*)d_out;

    cudaFuncSetAttribute(lstm_xproj, cudaFuncAttributeMaxDynamicSharedMemorySize, P1_SMEM);
    cudaFuncSetAttribute(lstm_rec,   cudaFuncAttributeMaxDynamicSharedMemorySize, SMEM2_BYTES);

    lstm_conv<<<1024, 256>>>(x, Wxi, Wxf, Wxc, Wxo);

    dim3 g1(32, 256);
    lstm_xproj<<<g1, 256, P1_SMEM>>>(bi, bf, bc, bo);

    lstm_rec<<<GRID2, 512, SMEM2_BYTES>>>(Whi, Whf, Whc, Who, out);
}